// round 2
// baseline (speedup 1.0000x reference)
#include <cuda_runtime.h>
#include <cuda_bf16.h>
#include <math.h>

// Problem constants
#define BATCH 2
#define TSEQ  2048
#define DIM   2048
#define NH    16
#define HD    128
#define MROWS (BATCH * TSEQ)      // 4096
#define KDIM  DIM                 // 2048

#define RESTORE_SCALE 45.25483399593904f   // sqrt(2048)
#define ATTN_SCALE    11.313708498984761f  // sqrt(128)

// ---------------------------------------------------------------------------
// Scratch (device globals — allocation-free rule)
// ---------------------------------------------------------------------------
__device__ float g_q[(size_t)BATCH * NH * TSEQ * HD];    // [B,H,T,HD]
__device__ float g_k[(size_t)BATCH * NH * TSEQ * HD];
__device__ float g_v[(size_t)BATCH * NH * TSEQ * HD];
__device__ float g_att[(size_t)MROWS * DIM];             // [B*T, DIM]

// ===========================================================================
// GEMM core: computes a 128x128 tile of C = A[M,K] * B[N,K]^T in fp32.
// 256 threads, 8x8 per thread (rows split 4+4, cols split 4+4 so every smem
// read is a conflict-free LDS.128). Double-buffered smem, GBK=16.
// Caller does the epilogue from acc[8][8].
//   row i (0..7) -> m = m0 + (i<4 ? ty4+i : 64+ty4+i-4)
//   col j (0..7) -> n = n0 + (j<4 ? tx4+j : 64+tx4+j-4)
// ===========================================================================
#define GBK 16
#define GPAD 132

__device__ __forceinline__ void gemm128_core(const float* __restrict__ A,
                                             const float* __restrict__ Bw,
                                             float acc[8][8])
{
    __shared__ float sA[2][GBK][GPAD];
    __shared__ float sB[2][GBK][GPAD];

    const int tid = threadIdx.x;
    const int tx4 = (tid & 15) * 4;
    const int ty4 = (tid >> 4) * 4;
    const int m0  = blockIdx.y * 128;
    const int n0  = blockIdx.x * 128;

    const int lm = tid >> 2;          // 0..63
    const int lk = (tid & 3) * 4;     // 0,4,8,12

    const float* Ag = A  + (size_t)(m0 + lm) * KDIM + lk;
    const float* Bg = Bw + (size_t)(n0 + lm) * KDIM + lk;

    float4 pa0 = *(const float4*)Ag;
    float4 pa1 = *(const float4*)(Ag + (size_t)64 * KDIM);
    float4 pb0 = *(const float4*)Bg;
    float4 pb1 = *(const float4*)(Bg + (size_t)64 * KDIM);

#pragma unroll
    for (int i = 0; i < 8; i++)
#pragma unroll
        for (int j = 0; j < 8; j++) acc[i][j] = 0.f;

    // stage 0
#pragma unroll
    for (int j = 0; j < 4; j++) {
        sA[0][lk + j][lm]      = ((const float*)&pa0)[j];
        sA[0][lk + j][64 + lm] = ((const float*)&pa1)[j];
        sB[0][lk + j][lm]      = ((const float*)&pb0)[j];
        sB[0][lk + j][64 + lm] = ((const float*)&pb1)[j];
    }
    __syncthreads();

    const int NKT = KDIM / GBK;       // 128
    for (int kt = 0; kt < NKT; ++kt) {
        const int cur = kt & 1;
        if (kt + 1 < NKT) {
            Ag += GBK; Bg += GBK;
            pa0 = *(const float4*)Ag;
            pa1 = *(const float4*)(Ag + (size_t)64 * KDIM);
            pb0 = *(const float4*)Bg;
            pb1 = *(const float4*)(Bg + (size_t)64 * KDIM);
        }
#pragma unroll
        for (int kk = 0; kk < GBK; ++kk) {
            float4 a0 = *(const float4*)&sA[cur][kk][ty4];
            float4 a1 = *(const float4*)&sA[cur][kk][64 + ty4];
            float4 b0 = *(const float4*)&sB[cur][kk][tx4];
            float4 b1 = *(const float4*)&sB[cur][kk][64 + tx4];
            float ar[8] = {a0.x, a0.y, a0.z, a0.w, a1.x, a1.y, a1.z, a1.w};
            float bc[8] = {b0.x, b0.y, b0.z, b0.w, b1.x, b1.y, b1.z, b1.w};
#pragma unroll
            for (int i = 0; i < 8; i++)
#pragma unroll
                for (int j = 0; j < 8; j++)
                    acc[i][j] = fmaf(ar[i], bc[j], acc[i][j]);
        }
        if (kt + 1 < NKT) {
            const int nxt = cur ^ 1;
#pragma unroll
            for (int j = 0; j < 4; j++) {
                sA[nxt][lk + j][lm]      = ((const float*)&pa0)[j];
                sA[nxt][lk + j][64 + lm] = ((const float*)&pa1)[j];
                sB[nxt][lk + j][lm]      = ((const float*)&pb0)[j];
                sB[nxt][lk + j][64 + lm] = ((const float*)&pb1)[j];
            }
        }
        __syncthreads();
    }
}

// ---------------------------------------------------------------------------
// Kernel 1: fused QKV projection. grid = (16, 32, 3); z selects W / output.
// Epilogue writes [B,H,T,HD] layout into g_q/g_k/g_v.
// ---------------------------------------------------------------------------
__global__ __launch_bounds__(256, 2)
void qkv_proj_kernel(const float* __restrict__ x,
                     const float* __restrict__ Wq,
                     const float* __restrict__ Wk,
                     const float* __restrict__ Wv)
{
    const float* W;
    float* out;
    if (blockIdx.z == 0)      { W = Wq; out = g_q; }
    else if (blockIdx.z == 1) { W = Wk; out = g_k; }
    else                      { W = Wv; out = g_v; }

    float acc[8][8];
    gemm128_core(x, W, acc);

    const int tid = threadIdx.x;
    const int tx4 = (tid & 15) * 4;
    const int ty4 = (tid >> 4) * 4;
    const int m0  = blockIdx.y * 128;
    const int n0  = blockIdx.x * 128;

#pragma unroll
    for (int i = 0; i < 8; i++) {
        const int m = m0 + ((i < 4) ? (ty4 + i) : (64 + ty4 + i - 4));
        const int b = m >> 11;
        const int t = m & 2047;
#pragma unroll
        for (int gg = 0; gg < 2; gg++) {
            const int n = n0 + (gg ? (64 + tx4) : tx4);
            const int h = n >> 7;
            const int d = n & 127;
            float4 v = make_float4(acc[i][gg * 4 + 0], acc[i][gg * 4 + 1],
                                   acc[i][gg * 4 + 2], acc[i][gg * 4 + 3]);
            *(float4*)&out[(((size_t)(b * NH + h)) * TSEQ + t) * HD + d] = v;
        }
    }
}

// ---------------------------------------------------------------------------
// Kernel 2: RoPE + sqk*RESTORE_SCALE on q and k, in-place, [B,H,T,HD].
// grid = B*H*T blocks of 64 threads (one thread per rotation pair).
// ---------------------------------------------------------------------------
__global__ void rope_kernel(const float* __restrict__ sqk)
{
    const int row = blockIdx.x;       // 0 .. B*H*T-1
    const int j   = threadIdx.x;      // 0 .. 63
    const int bh  = row >> 11;
    const int t   = row & 2047;
    const int h   = bh & (NH - 1);
    const size_t base = (size_t)row * HD;

    // theta_j = 10000^(-j/64), angle in double for accuracy at t up to 2047.
    const double theta = exp(-(double)j * (9.210340371976184 / 64.0));
    const double ang   = (double)t * theta;
    double sd, cd;
    sincos(ang, &sd, &cd);
    const float c = (float)cd, s = (float)sd;

    const float s1 = sqk[h * HD + j]      * RESTORE_SCALE;
    const float s2 = sqk[h * HD + 64 + j] * RESTORE_SCALE;

    float qr = g_q[base + j], qi = g_q[base + 64 + j];
    g_q[base + j]      = (qr * c - qi * s) * s1;
    g_q[base + 64 + j] = (qr * s + qi * c) * s2;

    float kr = g_k[base + j], ki = g_k[base + 64 + j];
    g_k[base + j]      = (kr * c - ki * s) * s1;
    g_k[base + 64 + j] = (kr * s + ki * c) * s2;
}

// ---------------------------------------------------------------------------
// Kernel 3: causal flash attention. BR=64 q-rows per CTA, BC=64 kv tile.
// grid = (T/64, B*H), 256 threads, dynamic smem.
// Q/K stored transposed in smem ([d][row], pad 68) for conflict-free LDS.128.
// Output written to g_att in [B*T, DIM] layout.
// ---------------------------------------------------------------------------
#define F_QOFF 0
#define F_KOFF (128 * 68)
#define F_VOFF (2 * 128 * 68)
#define F_POFF (2 * 128 * 68 + 64 * 132)
#define F_MOFF (F_POFF + 64 * 68)
#define F_LOFF (F_MOFF + 64)
#define F_SMEM_FLOATS (F_LOFF + 64)
#define F_SMEM_BYTES (F_SMEM_FLOATS * 4)   // 121,344 B

__global__ __launch_bounds__(256, 1)
void flash_kernel()
{
    extern __shared__ float sm[];
    float* QsT = sm + F_QOFF;   // [128][68]
    float* KsT = sm + F_KOFF;   // [128][68]
    float* Vs  = sm + F_VOFF;   // [64][132]
    float* Ps  = sm + F_POFF;   // [64][68]
    float* ms  = sm + F_MOFF;
    float* ls  = sm + F_LOFF;

    const int tid = threadIdx.x;
    const int tx4 = (tid & 15) * 4;
    const int ty4 = (tid >> 4) * 4;
    const int i0  = blockIdx.x * 64;
    const int bh  = blockIdx.y;
    const int b   = bh >> 4;
    const int h   = bh & 15;
    const size_t base = (size_t)bh * TSEQ * HD;

    // Load Q tile (pre-scaled by sqrt(HD)) into transposed smem.
#pragma unroll
    for (int it = 0; it < 8; ++it) {
        const int f  = tid + it * 256;
        const int c  = f >> 5;
        const int d4 = (f & 31) << 2;
        float4 v = *(const float4*)&g_q[base + (size_t)(i0 + c) * HD + d4];
        QsT[(d4 + 0) * 68 + c] = v.x * ATTN_SCALE;
        QsT[(d4 + 1) * 68 + c] = v.y * ATTN_SCALE;
        QsT[(d4 + 2) * 68 + c] = v.z * ATTN_SCALE;
        QsT[(d4 + 3) * 68 + c] = v.w * ATTN_SCALE;
    }
    if (tid < 64) { ms[tid] = -1e30f; ls[tid] = 0.f; }

    float o_acc[4][8];
#pragma unroll
    for (int i = 0; i < 4; i++)
#pragma unroll
        for (int n = 0; n < 8; n++) o_acc[i][n] = 0.f;

    const int ntiles = (i0 >> 6) + 1;
    for (int jt = 0; jt < ntiles; ++jt) {
        const int j0 = jt << 6;
        __syncthreads();   // prior PV reads done; Q/stat init visible

        // Load K (transposed) and V tiles
#pragma unroll
        for (int it = 0; it < 8; ++it) {
            const int f  = tid + it * 256;
            const int c  = f >> 5;
            const int d4 = (f & 31) << 2;
            float4 kv = *(const float4*)&g_k[base + (size_t)(j0 + c) * HD + d4];
            KsT[(d4 + 0) * 68 + c] = kv.x;
            KsT[(d4 + 1) * 68 + c] = kv.y;
            KsT[(d4 + 2) * 68 + c] = kv.z;
            KsT[(d4 + 3) * 68 + c] = kv.w;
            float4 vv = *(const float4*)&g_v[base + (size_t)(j0 + c) * HD + d4];
            *(float4*)&Vs[c * 132 + d4] = vv;
        }
        __syncthreads();

        // S = Q K^T (4x4 per thread)
        float s[4][4];
#pragma unroll
        for (int i = 0; i < 4; i++)
#pragma unroll
            for (int j = 0; j < 4; j++) s[i][j] = 0.f;

#pragma unroll 4
        for (int d = 0; d < 128; ++d) {
            float4 qa = *(const float4*)&QsT[d * 68 + ty4];
            float4 kb = *(const float4*)&KsT[d * 68 + tx4];
            float qr[4] = {qa.x, qa.y, qa.z, qa.w};
            float kc[4] = {kb.x, kb.y, kb.z, kb.w};
#pragma unroll
            for (int i = 0; i < 4; i++)
#pragma unroll
                for (int j = 0; j < 4; j++)
                    s[i][j] = fmaf(qr[i], kc[j], s[i][j]);
        }

        if (j0 == i0) {  // diagonal tile: causal mask
#pragma unroll
            for (int i = 0; i < 4; i++)
#pragma unroll
                for (int j = 0; j < 4; j++)
                    if (tx4 + j > ty4 + i) s[i][j] = -1e30f;
        }

        // online softmax (per 4 owned rows; reduce across 16-lane tx group)
        float al[4];
#pragma unroll
        for (int i = 0; i < 4; i++) {
            float rm = fmaxf(fmaxf(s[i][0], s[i][1]), fmaxf(s[i][2], s[i][3]));
            rm = fmaxf(rm, __shfl_xor_sync(0xffffffffu, rm, 1));
            rm = fmaxf(rm, __shfl_xor_sync(0xffffffffu, rm, 2));
            rm = fmaxf(rm, __shfl_xor_sync(0xffffffffu, rm, 4));
            rm = fmaxf(rm, __shfl_xor_sync(0xffffffffu, rm, 8));
            const float mo = ms[ty4 + i];
            const float mn = fmaxf(mo, rm);
            al[i] = __expf(mo - mn);
            float r = 0.f;
#pragma unroll
            for (int j = 0; j < 4; j++) {
                const float p = __expf(s[i][j] - mn);
                Ps[(tx4 + j) * 68 + ty4 + i] = p;
                r += p;
            }
            r += __shfl_xor_sync(0xffffffffu, r, 1);
            r += __shfl_xor_sync(0xffffffffu, r, 2);
            r += __shfl_xor_sync(0xffffffffu, r, 4);
            r += __shfl_xor_sync(0xffffffffu, r, 8);
            // identical value written by the whole tx-group: benign
            ls[ty4 + i] = ls[ty4 + i] * al[i] + r;
            ms[ty4 + i] = mn;
        }
#pragma unroll
        for (int i = 0; i < 4; i++)
#pragma unroll
            for (int n = 0; n < 8; n++) o_acc[i][n] *= al[i];

        __syncthreads();   // Ps visible to everyone

        // O += P * V
#pragma unroll 4
        for (int c = 0; c < 64; ++c) {
            float4 p4 = *(const float4*)&Ps[c * 68 + ty4];
            float4 va = *(const float4*)&Vs[c * 132 + tx4];
            float4 vb = *(const float4*)&Vs[c * 132 + 64 + tx4];
            float pr[4] = {p4.x, p4.y, p4.z, p4.w};
#pragma unroll
            for (int i = 0; i < 4; i++) {
                o_acc[i][0] = fmaf(pr[i], va.x, o_acc[i][0]);
                o_acc[i][1] = fmaf(pr[i], va.y, o_acc[i][1]);
                o_acc[i][2] = fmaf(pr[i], va.z, o_acc[i][2]);
                o_acc[i][3] = fmaf(pr[i], va.w, o_acc[i][3]);
                o_acc[i][4] = fmaf(pr[i], vb.x, o_acc[i][4]);
                o_acc[i][5] = fmaf(pr[i], vb.y, o_acc[i][5]);
                o_acc[i][6] = fmaf(pr[i], vb.z, o_acc[i][6]);
                o_acc[i][7] = fmaf(pr[i], vb.w, o_acc[i][7]);
            }
        }
    }

    // Epilogue: normalize by l, write to [B*T, DIM] layout
#pragma unroll
    for (int i = 0; i < 4; i++) {
        const float inv = 1.0f / ls[ty4 + i];
        const int row = i0 + ty4 + i;
        float* dst = &g_att[((size_t)(b * TSEQ + row)) * DIM + h * HD];
        float4 w0 = make_float4(o_acc[i][0] * inv, o_acc[i][1] * inv,
                                o_acc[i][2] * inv, o_acc[i][3] * inv);
        float4 w1 = make_float4(o_acc[i][4] * inv, o_acc[i][5] * inv,
                                o_acc[i][6] * inv, o_acc[i][7] * inv);
        *(float4*)&dst[tx4]      = w0;
        *(float4*)&dst[64 + tx4] = w1;
    }
}

// ---------------------------------------------------------------------------
// Kernel 4: output projection y = att @ Wo^T   (plain row-major epilogue)
// ---------------------------------------------------------------------------
__global__ __launch_bounds__(256, 2)
void out_proj_kernel(const float* __restrict__ Wo, float* __restrict__ y)
{
    float acc[8][8];
    gemm128_core(g_att, Wo, acc);

    const int tid = threadIdx.x;
    const int tx4 = (tid & 15) * 4;
    const int ty4 = (tid >> 4) * 4;
    const int m0  = blockIdx.y * 128;
    const int n0  = blockIdx.x * 128;

#pragma unroll
    for (int i = 0; i < 8; i++) {
        const int m = m0 + ((i < 4) ? (ty4 + i) : (64 + ty4 + i - 4));
#pragma unroll
        for (int gg = 0; gg < 2; gg++) {
            const int n = n0 + (gg ? (64 + tx4) : tx4);
            float4 v = make_float4(acc[i][gg * 4 + 0], acc[i][gg * 4 + 1],
                                   acc[i][gg * 4 + 2], acc[i][gg * 4 + 3]);
            *(float4*)&y[(size_t)m * DIM + n] = v;
        }
    }
}

// ---------------------------------------------------------------------------
// Kernel 5: per-row L2 normalization of y (in place on d_out)
// ---------------------------------------------------------------------------
__global__ void norm_kernel(float* __restrict__ y)
{
    const int row = blockIdx.x;
    float4* p = (float4*)(y + (size_t)row * DIM);
    float ss = 0.f;
#pragma unroll
    for (int i = threadIdx.x; i < DIM / 4; i += 256) {
        float4 v = p[i];
        ss += v.x * v.x + v.y * v.y + v.z * v.z + v.w * v.w;
    }
    ss += __shfl_xor_sync(0xffffffffu, ss, 16);
    ss += __shfl_xor_sync(0xffffffffu, ss, 8);
    ss += __shfl_xor_sync(0xffffffffu, ss, 4);
    ss += __shfl_xor_sync(0xffffffffu, ss, 2);
    ss += __shfl_xor_sync(0xffffffffu, ss, 1);
    __shared__ float red[8];
    if ((threadIdx.x & 31) == 0) red[threadIdx.x >> 5] = ss;
    __syncthreads();
    float tot = red[0] + red[1] + red[2] + red[3] +
                red[4] + red[5] + red[6] + red[7];
    const float inv = 1.0f / fmaxf(sqrtf(tot), 1e-12f);
#pragma unroll
    for (int i = threadIdx.x; i < DIM / 4; i += 256) {
        float4 v = p[i];
        v.x *= inv; v.y *= inv; v.z *= inv; v.w *= inv;
        p[i] = v;
    }
}

// ---------------------------------------------------------------------------
// Launch
// ---------------------------------------------------------------------------
extern "C" void kernel_launch(void* const* d_in, const int* in_sizes, int n_in,
                              void* d_out, int out_size)
{
    const float* x   = (const float*)d_in[0];
    const float* Wq  = (const float*)d_in[1];
    const float* Wk  = (const float*)d_in[2];
    const float* Wv  = (const float*)d_in[3];
    const float* Wo  = (const float*)d_in[4];
    const float* sqk = (const float*)d_in[5];
    float* y = (float*)d_out;

    cudaFuncSetAttribute(flash_kernel,
                         cudaFuncAttributeMaxDynamicSharedMemorySize,
                         F_SMEM_BYTES);

    qkv_proj_kernel<<<dim3(DIM / 128, MROWS / 128, 3), 256>>>(x, Wq, Wk, Wv);
    rope_kernel<<<BATCH * NH * TSEQ, 64>>>(sqk);
    flash_kernel<<<dim3(TSEQ / 64, BATCH * NH), 256, F_SMEM_BYTES>>>();
    out_proj_kernel<<<dim3(DIM / 128, MROWS / 128), 256>>>(Wo, y);
    norm_kernel<<<MROWS, 256>>>(y);
}

// round 4
// speedup vs baseline: 1.2139x; 1.2139x over previous
#include <cuda_runtime.h>
#include <cuda_bf16.h>
#include <math.h>
#include <stdint.h>

// Problem constants
#define BATCH 2
#define TSEQ  2048
#define DIM   2048
#define NH    16
#define HD    128
#define MROWS (BATCH * TSEQ)      // 4096
#define KDIM  DIM                 // 2048

#define RESTORE_SCALE 45.25483399593904f   // sqrt(2048)
#define ATTN_SCALE    11.313708498984761f  // sqrt(128)

// ---------------------------------------------------------------------------
// Scratch (device globals — allocation-free rule)
// ---------------------------------------------------------------------------
__device__ float g_q[(size_t)BATCH * NH * TSEQ * HD];    // [B,H,T,HD]
__device__ float g_k[(size_t)BATCH * NH * TSEQ * HD];
__device__ float g_v[(size_t)BATCH * NH * TSEQ * HD];
__device__ float g_att[(size_t)MROWS * DIM];             // [B*T, DIM]

// ---------------------------------------------------------------------------
// PTX helpers (base-target-safe: ldmatrix + mma.sync only)
// ---------------------------------------------------------------------------
__device__ __forceinline__ uint32_t smem_u32(const void* p) {
    uint32_t a;
    asm("{ .reg .u64 t; cvta.to.shared.u64 t, %1; cvt.u32.u64 %0, t; }"
        : "=r"(a) : "l"(p));
    return a;
}

__device__ __forceinline__ void ldsm4(uint32_t addr, uint32_t r[4]) {
    asm volatile("ldmatrix.sync.aligned.m8n8.x4.shared.b16 {%0,%1,%2,%3}, [%4];"
        : "=r"(r[0]), "=r"(r[1]), "=r"(r[2]), "=r"(r[3]) : "r"(addr));
}

__device__ __forceinline__ void mma16816(float c[4], const uint32_t a[4],
                                         uint32_t b0, uint32_t b1) {
    asm volatile(
        "mma.sync.aligned.m16n8k16.row.col.f32.bf16.bf16.f32 "
        "{%0,%1,%2,%3}, {%4,%5,%6,%7}, {%8,%9}, {%0,%1,%2,%3};"
        : "+f"(c[0]), "+f"(c[1]), "+f"(c[2]), "+f"(c[3])
        : "r"(a[0]), "r"(a[1]), "r"(a[2]), "r"(a[3]), "r"(b0), "r"(b1));
}

// ===========================================================================
// HMMA bf16x3 GEMM: C[128x128 tile] = A[M,K] * W[N,K]^T (fp32-accurate)
// 256 threads / 8 warps (4M x 2N), warp tile 32x64, K-chunk 32,
// double-buffered smem (hi/lo split for A and B), row stride 80 B.
// MODE 0: QKV projection (blockIdx.z selects W, scatter to [B,H,T,HD]).
// MODE 1: out projection (row-major epilogue to y).
// ===========================================================================
#define KC 32
#define NKC (KDIM / KC)            // 64
#define ROWB 80                    // bytes per smem row (32 bf16 + pad)
#define MAT_BYTES (128 * ROWB)     // 10240
#define STAGE_BYTES (4 * MAT_BYTES)
#define G_SMEM_BYTES (2 * STAGE_BYTES)   // 81920

// Load 16 consecutive fp32, split to bf16 hi/lo packed as uint4 pairs.
__device__ __forceinline__ void load_convert(const float* __restrict__ p,
                                             uint4 hi[2], uint4 lo[2])
{
    float4 v0 = ((const float4*)p)[0];
    float4 v1 = ((const float4*)p)[1];
    float4 v2 = ((const float4*)p)[2];
    float4 v3 = ((const float4*)p)[3];
    float f[16] = {v0.x, v0.y, v0.z, v0.w, v1.x, v1.y, v1.z, v1.w,
                   v2.x, v2.y, v2.z, v2.w, v3.x, v3.y, v3.z, v3.w};
    union { __nv_bfloat162 b[8]; uint4 u[2]; } H, L;
#pragma unroll
    for (int j = 0; j < 8; ++j) {
        float a = f[2 * j], b = f[2 * j + 1];
        __nv_bfloat16 ah = __float2bfloat16_rn(a);
        __nv_bfloat16 bh = __float2bfloat16_rn(b);
        __nv_bfloat16 al = __float2bfloat16_rn(a - __bfloat162float(ah));
        __nv_bfloat16 bl = __float2bfloat16_rn(b - __bfloat162float(bh));
        H.b[j] = __halves2bfloat162(ah, bh);
        L.b[j] = __halves2bfloat162(al, bl);
    }
    hi[0] = H.u[0]; hi[1] = H.u[1];
    lo[0] = L.u[0]; lo[1] = L.u[1];
}

template <int MODE>
__global__ __launch_bounds__(256, 1)
void gemm_hmma_kernel(const float* __restrict__ x,
                      const float* __restrict__ W0,
                      const float* __restrict__ W1,
                      const float* __restrict__ W2,
                      float* __restrict__ yout)
{
    extern __shared__ char sm[];
    const uint32_t sb = smem_u32(sm);
    const int tid  = threadIdx.x;
    const int wid  = tid >> 5;
    const int lane = tid & 31;
    const int m0   = blockIdx.y * 128;
    const int n0   = blockIdx.x * 128;

    const float* A;
    const float* Bw;
    float* out;
    if (MODE == 0) {
        A = x;
        if (blockIdx.z == 0)      { Bw = W0; out = g_q; }
        else if (blockIdx.z == 1) { Bw = W1; out = g_k; }
        else                      { Bw = W2; out = g_v; }
    } else {
        A = g_att; Bw = W0; out = yout;
    }

    // per-thread global pointers: row = tid>>1 (128 rows), col half = (tid&1)*16
    const float* Ag = A  + (size_t)(m0 + (tid >> 1)) * KDIM + (tid & 1) * 16;
    const float* Bg = Bw + (size_t)(n0 + (tid >> 1)) * KDIM + (tid & 1) * 16;
    const uint32_t sto = (uint32_t)((tid >> 1) * ROWB + (tid & 1) * 32);

    // warp tiling: wm in 0..3 (M by 32), wn in 0..1 (N by 64)
    const int wm = wid & 3;
    const int wn = wid >> 2;
    const int r   = lane & 7;
    const int sel = lane >> 3;
    // ldmatrix lane base offsets (bytes, within a matrix, before ks/k-tile adds)
    const uint32_t aBase = (uint32_t)((wm * 32 + r + (sel & 1) * 8) * ROWB +
                                      ((sel >> 1) * 8) * 2);
    const uint32_t bBase = (uint32_t)((wn * 64 + r + (sel >> 1) * 8) * ROWB +
                                      ((sel & 1) * 8) * 2);

    float acc[2][8][4];
#pragma unroll
    for (int i = 0; i < 2; i++)
#pragma unroll
        for (int j = 0; j < 8; j++)
#pragma unroll
            for (int t = 0; t < 4; t++) acc[i][j][t] = 0.f;

    uint4 pahi[2], palo[2], pbhi[2], pblo[2];
    load_convert(Ag, pahi, palo);
    load_convert(Bg, pbhi, pblo);
    {
        char* st = sm;   // stage 0
        *(uint4*)(st + sto)                       = pahi[0];
        *(uint4*)(st + sto + 16)                  = pahi[1];
        *(uint4*)(st + MAT_BYTES + sto)           = palo[0];
        *(uint4*)(st + MAT_BYTES + sto + 16)      = palo[1];
        *(uint4*)(st + 2 * MAT_BYTES + sto)       = pbhi[0];
        *(uint4*)(st + 2 * MAT_BYTES + sto + 16)  = pbhi[1];
        *(uint4*)(st + 3 * MAT_BYTES + sto)       = pblo[0];
        *(uint4*)(st + 3 * MAT_BYTES + sto + 16)  = pblo[1];
    }
    __syncthreads();

    for (int kc = 0; kc < NKC; ++kc) {
        const int cur = kc & 1;
        if (kc + 1 < NKC) {
            load_convert(Ag + (kc + 1) * KC, pahi, palo);
            load_convert(Bg + (kc + 1) * KC, pbhi, pblo);
        }
        const uint32_t stage = sb + cur * STAGE_BYTES;

#pragma unroll
        for (int ks = 0; ks < 2; ++ks) {
            const uint32_t koff = ks * 32;   // 16 bf16 = 32 bytes
            uint32_t ah[2][4], al[2][4];
#pragma unroll
            for (int i = 0; i < 2; ++i) {
                const uint32_t aA = stage + aBase + i * (16 * ROWB) + koff;
                ldsm4(aA, ah[i]);
                ldsm4(aA + MAT_BYTES, al[i]);
            }
#pragma unroll
            for (int j = 0; j < 4; ++j) {
                const uint32_t bA = stage + 2 * MAT_BYTES + bBase +
                                    j * (16 * ROWB) + koff;
                uint32_t bh[4], bl[4];
                ldsm4(bA, bh);
                ldsm4(bA + MAT_BYTES, bl);
#pragma unroll
                for (int i = 0; i < 2; ++i) {
#pragma unroll
                    for (int t = 0; t < 2; ++t) {
                        mma16816(acc[i][j * 2 + t], ah[i], bh[2 * t], bh[2 * t + 1]);
                        mma16816(acc[i][j * 2 + t], ah[i], bl[2 * t], bl[2 * t + 1]);
                        mma16816(acc[i][j * 2 + t], al[i], bh[2 * t], bh[2 * t + 1]);
                    }
                }
            }
        }

        if (kc + 1 < NKC) {
            char* st = sm + (cur ^ 1) * STAGE_BYTES;
            *(uint4*)(st + sto)                       = pahi[0];
            *(uint4*)(st + sto + 16)                  = pahi[1];
            *(uint4*)(st + MAT_BYTES + sto)           = palo[0];
            *(uint4*)(st + MAT_BYTES + sto + 16)      = palo[1];
            *(uint4*)(st + 2 * MAT_BYTES + sto)       = pbhi[0];
            *(uint4*)(st + 2 * MAT_BYTES + sto + 16)  = pbhi[1];
            *(uint4*)(st + 3 * MAT_BYTES + sto)       = pblo[0];
            *(uint4*)(st + 3 * MAT_BYTES + sto + 16)  = pblo[1];
        }
        __syncthreads();
    }

    // Epilogue. acc[i][j]: rows m0+wm*32+i*16+(lane>>2) (+8), cols
    // n0+wn*64+j*8+2*(lane&3).
#pragma unroll
    for (int i = 0; i < 2; ++i) {
        const int mrow = m0 + wm * 32 + i * 16 + (lane >> 2);
#pragma unroll
        for (int j = 0; j < 8; ++j) {
            const int ncol = n0 + wn * 64 + j * 8 + 2 * (lane & 3);
            float2 v01 = make_float2(acc[i][j][0], acc[i][j][1]);
            float2 v23 = make_float2(acc[i][j][2], acc[i][j][3]);
            if (MODE == 0) {
                const int b = mrow >> 11;
                const int t = mrow & 2047;
                const int h = ncol >> 7;
                const int d = ncol & 127;
                float* dst = &out[(((size_t)(b * NH + h)) * TSEQ + t) * HD + d];
                *(float2*)dst = v01;
                *(float2*)(dst + (size_t)8 * HD) = v23;
            } else {
                float* dst = &out[(size_t)mrow * DIM + ncol];
                *(float2*)dst = v01;
                *(float2*)(dst + (size_t)8 * DIM) = v23;
            }
        }
    }
}

// ---------------------------------------------------------------------------
// Kernel 2: RoPE + sqk*RESTORE_SCALE on q and k, in-place, [B,H,T,HD].
// ---------------------------------------------------------------------------
__global__ void rope_kernel(const float* __restrict__ sqk)
{
    const int row = blockIdx.x;       // 0 .. B*H*T-1
    const int j   = threadIdx.x;      // 0 .. 63
    const int bh  = row >> 11;
    const int t   = row & 2047;
    const int h   = bh & (NH - 1);
    const size_t base = (size_t)row * HD;

    const double theta = exp(-(double)j * (9.210340371976184 / 64.0));
    const double ang   = (double)t * theta;
    double sd, cd;
    sincos(ang, &sd, &cd);
    const float c = (float)cd, s = (float)sd;

    const float s1 = sqk[h * HD + j]      * RESTORE_SCALE;
    const float s2 = sqk[h * HD + 64 + j] * RESTORE_SCALE;

    float qr = g_q[base + j], qi = g_q[base + 64 + j];
    g_q[base + j]      = (qr * c - qi * s) * s1;
    g_q[base + 64 + j] = (qr * s + qi * c) * s2;

    float kr = g_k[base + j], ki = g_k[base + 64 + j];
    g_k[base + j]      = (kr * c - ki * s) * s1;
    g_k[base + 64 + j] = (kr * s + ki * c) * s2;
}

// ---------------------------------------------------------------------------
// Kernel 3: causal flash attention (fp32 SIMT). BR=64, BC=64, 256 threads.
// ---------------------------------------------------------------------------
#define F_QOFF 0
#define F_KOFF (128 * 68)
#define F_VOFF (2 * 128 * 68)
#define F_POFF (2 * 128 * 68 + 64 * 132)
#define F_MOFF (F_POFF + 64 * 68)
#define F_LOFF (F_MOFF + 64)
#define F_SMEM_FLOATS (F_LOFF + 64)
#define F_SMEM_BYTES (F_SMEM_FLOATS * 4)   // 121,344 B

__global__ __launch_bounds__(256, 1)
void flash_kernel()
{
    extern __shared__ float smf[];
    float* QsT = smf + F_QOFF;   // [128][68]
    float* KsT = smf + F_KOFF;   // [128][68]
    float* Vs  = smf + F_VOFF;   // [64][132]
    float* Ps  = smf + F_POFF;   // [64][68]
    float* ms  = smf + F_MOFF;
    float* ls  = smf + F_LOFF;

    const int tid = threadIdx.x;
    const int tx4 = (tid & 15) * 4;
    const int ty4 = (tid >> 4) * 4;
    const int i0  = blockIdx.x * 64;
    const int bh  = blockIdx.y;
    const int b   = bh >> 4;
    const int h   = bh & 15;
    const size_t base = (size_t)bh * TSEQ * HD;

#pragma unroll
    for (int it = 0; it < 8; ++it) {
        const int f  = tid + it * 256;
        const int c  = f >> 5;
        const int d4 = (f & 31) << 2;
        float4 v = *(const float4*)&g_q[base + (size_t)(i0 + c) * HD + d4];
        QsT[(d4 + 0) * 68 + c] = v.x * ATTN_SCALE;
        QsT[(d4 + 1) * 68 + c] = v.y * ATTN_SCALE;
        QsT[(d4 + 2) * 68 + c] = v.z * ATTN_SCALE;
        QsT[(d4 + 3) * 68 + c] = v.w * ATTN_SCALE;
    }
    if (tid < 64) { ms[tid] = -1e30f; ls[tid] = 0.f; }

    float o_acc[4][8];
#pragma unroll
    for (int i = 0; i < 4; i++)
#pragma unroll
        for (int n = 0; n < 8; n++) o_acc[i][n] = 0.f;

    const int ntiles = (i0 >> 6) + 1;
    for (int jt = 0; jt < ntiles; ++jt) {
        const int j0 = jt << 6;
        __syncthreads();

#pragma unroll
        for (int it = 0; it < 8; ++it) {
            const int f  = tid + it * 256;
            const int c  = f >> 5;
            const int d4 = (f & 31) << 2;
            float4 kv = *(const float4*)&g_k[base + (size_t)(j0 + c) * HD + d4];
            KsT[(d4 + 0) * 68 + c] = kv.x;
            KsT[(d4 + 1) * 68 + c] = kv.y;
            KsT[(d4 + 2) * 68 + c] = kv.z;
            KsT[(d4 + 3) * 68 + c] = kv.w;
            float4 vv = *(const float4*)&g_v[base + (size_t)(j0 + c) * HD + d4];
            *(float4*)&Vs[c * 132 + d4] = vv;
        }
        __syncthreads();

        float s[4][4];
#pragma unroll
        for (int i = 0; i < 4; i++)
#pragma unroll
            for (int j = 0; j < 4; j++) s[i][j] = 0.f;

#pragma unroll 4
        for (int d = 0; d < 128; ++d) {
            float4 qa = *(const float4*)&QsT[d * 68 + ty4];
            float4 kb = *(const float4*)&KsT[d * 68 + tx4];
            float qr[4] = {qa.x, qa.y, qa.z, qa.w};
            float kc[4] = {kb.x, kb.y, kb.z, kb.w};
#pragma unroll
            for (int i = 0; i < 4; i++)
#pragma unroll
                for (int j = 0; j < 4; j++)
                    s[i][j] = fmaf(qr[i], kc[j], s[i][j]);
        }

        if (j0 == i0) {
#pragma unroll
            for (int i = 0; i < 4; i++)
#pragma unroll
                for (int j = 0; j < 4; j++)
                    if (tx4 + j > ty4 + i) s[i][j] = -1e30f;
        }

        float al[4];
#pragma unroll
        for (int i = 0; i < 4; i++) {
            float rm = fmaxf(fmaxf(s[i][0], s[i][1]), fmaxf(s[i][2], s[i][3]));
            rm = fmaxf(rm, __shfl_xor_sync(0xffffffffu, rm, 1));
            rm = fmaxf(rm, __shfl_xor_sync(0xffffffffu, rm, 2));
            rm = fmaxf(rm, __shfl_xor_sync(0xffffffffu, rm, 4));
            rm = fmaxf(rm, __shfl_xor_sync(0xffffffffu, rm, 8));
            const float mo = ms[ty4 + i];
            const float mn = fmaxf(mo, rm);
            al[i] = __expf(mo - mn);
            float r = 0.f;
#pragma unroll
            for (int j = 0; j < 4; j++) {
                const float p = __expf(s[i][j] - mn);
                Ps[(tx4 + j) * 68 + ty4 + i] = p;
                r += p;
            }
            r += __shfl_xor_sync(0xffffffffu, r, 1);
            r += __shfl_xor_sync(0xffffffffu, r, 2);
            r += __shfl_xor_sync(0xffffffffu, r, 4);
            r += __shfl_xor_sync(0xffffffffu, r, 8);
            ls[ty4 + i] = ls[ty4 + i] * al[i] + r;
            ms[ty4 + i] = mn;
        }
#pragma unroll
        for (int i = 0; i < 4; i++)
#pragma unroll
            for (int n = 0; n < 8; n++) o_acc[i][n] *= al[i];

        __syncthreads();

#pragma unroll 4
        for (int c = 0; c < 64; ++c) {
            float4 p4 = *(const float4*)&Ps[c * 68 + ty4];
            float4 va = *(const float4*)&Vs[c * 132 + tx4];
            float4 vb = *(const float4*)&Vs[c * 132 + 64 + tx4];
            float pr[4] = {p4.x, p4.y, p4.z, p4.w};
#pragma unroll
            for (int i = 0; i < 4; i++) {
                o_acc[i][0] = fmaf(pr[i], va.x, o_acc[i][0]);
                o_acc[i][1] = fmaf(pr[i], va.y, o_acc[i][1]);
                o_acc[i][2] = fmaf(pr[i], va.z, o_acc[i][2]);
                o_acc[i][3] = fmaf(pr[i], va.w, o_acc[i][3]);
                o_acc[i][4] = fmaf(pr[i], vb.x, o_acc[i][4]);
                o_acc[i][5] = fmaf(pr[i], vb.y, o_acc[i][5]);
                o_acc[i][6] = fmaf(pr[i], vb.z, o_acc[i][6]);
                o_acc[i][7] = fmaf(pr[i], vb.w, o_acc[i][7]);
            }
        }
    }

#pragma unroll
    for (int i = 0; i < 4; i++) {
        const float inv = 1.0f / ls[ty4 + i];
        const int row = i0 + ty4 + i;
        float* dst = &g_att[((size_t)(b * TSEQ + row)) * DIM + h * HD];
        float4 w0 = make_float4(o_acc[i][0] * inv, o_acc[i][1] * inv,
                                o_acc[i][2] * inv, o_acc[i][3] * inv);
        float4 w1 = make_float4(o_acc[i][4] * inv, o_acc[i][5] * inv,
                                o_acc[i][6] * inv, o_acc[i][7] * inv);
        *(float4*)&dst[tx4]      = w0;
        *(float4*)&dst[64 + tx4] = w1;
    }
}

// ---------------------------------------------------------------------------
// Kernel 5: per-row L2 normalization of y (in place on d_out)
// ---------------------------------------------------------------------------
__global__ void norm_kernel(float* __restrict__ y)
{
    const int row = blockIdx.x;
    float4* p = (float4*)(y + (size_t)row * DIM);
    float ss = 0.f;
#pragma unroll
    for (int i = threadIdx.x; i < DIM / 4; i += 256) {
        float4 v = p[i];
        ss += v.x * v.x + v.y * v.y + v.z * v.z + v.w * v.w;
    }
    ss += __shfl_xor_sync(0xffffffffu, ss, 16);
    ss += __shfl_xor_sync(0xffffffffu, ss, 8);
    ss += __shfl_xor_sync(0xffffffffu, ss, 4);
    ss += __shfl_xor_sync(0xffffffffu, ss, 2);
    ss += __shfl_xor_sync(0xffffffffu, ss, 1);
    __shared__ float red[8];
    if ((threadIdx.x & 31) == 0) red[threadIdx.x >> 5] = ss;
    __syncthreads();
    float tot = red[0] + red[1] + red[2] + red[3] +
                red[4] + red[5] + red[6] + red[7];
    const float inv = 1.0f / fmaxf(sqrtf(tot), 1e-12f);
#pragma unroll
    for (int i = threadIdx.x; i < DIM / 4; i += 256) {
        float4 v = p[i];
        v.x *= inv; v.y *= inv; v.z *= inv; v.w *= inv;
        p[i] = v;
    }
}

// ---------------------------------------------------------------------------
// Launch
// ---------------------------------------------------------------------------
extern "C" void kernel_launch(void* const* d_in, const int* in_sizes, int n_in,
                              void* d_out, int out_size)
{
    const float* x   = (const float*)d_in[0];
    const float* Wq  = (const float*)d_in[1];
    const float* Wk  = (const float*)d_in[2];
    const float* Wv  = (const float*)d_in[3];
    const float* Wo  = (const float*)d_in[4];
    const float* sqk = (const float*)d_in[5];
    float* y = (float*)d_out;

    cudaFuncSetAttribute(flash_kernel,
                         cudaFuncAttributeMaxDynamicSharedMemorySize,
                         F_SMEM_BYTES);
    cudaFuncSetAttribute(gemm_hmma_kernel<0>,
                         cudaFuncAttributeMaxDynamicSharedMemorySize,
                         G_SMEM_BYTES);
    cudaFuncSetAttribute(gemm_hmma_kernel<1>,
                         cudaFuncAttributeMaxDynamicSharedMemorySize,
                         G_SMEM_BYTES);

    gemm_hmma_kernel<0><<<dim3(DIM / 128, MROWS / 128, 3), 256, G_SMEM_BYTES>>>(
        x, Wq, Wk, Wv, nullptr);
    rope_kernel<<<BATCH * NH * TSEQ, 64>>>(sqk);
    flash_kernel<<<dim3(TSEQ / 64, BATCH * NH), 256, F_SMEM_BYTES>>>();
    gemm_hmma_kernel<1><<<dim3(DIM / 128, MROWS / 128, 1), 256, G_SMEM_BYTES>>>(
        nullptr, Wo, nullptr, nullptr, y);
    norm_kernel<<<MROWS, 256>>>(y);
}

// round 5
// speedup vs baseline: 2.2159x; 1.8254x over previous
#include <cuda_runtime.h>
#include <cuda_bf16.h>
#include <math.h>
#include <stdint.h>

// Problem constants
#define BATCH 2
#define TSEQ  2048
#define DIM   2048
#define NH    16
#define HD    128
#define MROWS (BATCH * TSEQ)      // 4096
#define KDIM  DIM                 // 2048
#define NELEM ((size_t)BATCH * NH * TSEQ * HD)   // 8.4M

#define RESTORE_SCALE 45.25483399593904f   // sqrt(2048)
#define ATTN_SCALE    11.313708498984761f  // sqrt(128)

// ---------------------------------------------------------------------------
// Scratch (device globals — allocation-free rule)
// ---------------------------------------------------------------------------
__device__ float g_q[NELEM];                 // [B,H,T,HD] fp32 (pre-rope)
__device__ float g_k[NELEM];
__device__ float g_v[NELEM];

__device__ __nv_bfloat16 g_xh[(size_t)MROWS * DIM], g_xl[(size_t)MROWS * DIM];
__device__ __nv_bfloat16 g_wqh[(size_t)DIM * DIM], g_wql[(size_t)DIM * DIM];
__device__ __nv_bfloat16 g_wkh[(size_t)DIM * DIM], g_wkl[(size_t)DIM * DIM];
__device__ __nv_bfloat16 g_wvh[(size_t)DIM * DIM], g_wvl[(size_t)DIM * DIM];
__device__ __nv_bfloat16 g_woh[(size_t)DIM * DIM], g_wol[(size_t)DIM * DIM];

__device__ __nv_bfloat16 g_qh[NELEM], g_ql[NELEM];   // roped+scaled q
__device__ __nv_bfloat16 g_kh[NELEM], g_kl[NELEM];   // roped+scaled k
__device__ __nv_bfloat16 g_vh[NELEM], g_vl[NELEM];   // v
__device__ __nv_bfloat16 g_ah[(size_t)MROWS * DIM], g_al[(size_t)MROWS * DIM]; // attn out

// ---------------------------------------------------------------------------
// PTX helpers (base sm_103 target safe: ldmatrix / mma.sync / cp.async)
// ---------------------------------------------------------------------------
__device__ __forceinline__ uint32_t smem_u32(const void* p) {
    uint32_t a;
    asm("{ .reg .u64 t; cvta.to.shared.u64 t, %1; cvt.u32.u64 %0, t; }"
        : "=r"(a) : "l"(p));
    return a;
}
__device__ __forceinline__ void ldsm4(uint32_t addr, uint32_t r[4]) {
    asm volatile("ldmatrix.sync.aligned.m8n8.x4.shared.b16 {%0,%1,%2,%3}, [%4];"
        : "=r"(r[0]), "=r"(r[1]), "=r"(r[2]), "=r"(r[3]) : "r"(addr));
}
__device__ __forceinline__ void ldsm4t(uint32_t addr, uint32_t r[4]) {
    asm volatile("ldmatrix.sync.aligned.m8n8.x4.trans.shared.b16 {%0,%1,%2,%3}, [%4];"
        : "=r"(r[0]), "=r"(r[1]), "=r"(r[2]), "=r"(r[3]) : "r"(addr));
}
__device__ __forceinline__ void mma16816(float c[4], const uint32_t a[4],
                                         uint32_t b0, uint32_t b1) {
    asm volatile(
        "mma.sync.aligned.m16n8k16.row.col.f32.bf16.bf16.f32 "
        "{%0,%1,%2,%3}, {%4,%5,%6,%7}, {%8,%9}, {%0,%1,%2,%3};"
        : "+f"(c[0]), "+f"(c[1]), "+f"(c[2]), "+f"(c[3])
        : "r"(a[0]), "r"(a[1]), "r"(a[2]), "r"(a[3]), "r"(b0), "r"(b1));
}
#define CP16(dst, src) \
    asm volatile("cp.async.cg.shared.global [%0], [%1], 16;" \
        :: "r"(dst), "l"(src))
#define CP_COMMIT() asm volatile("cp.async.commit_group;" ::: "memory")
#define CP_WAIT1()  asm volatile("cp.async.wait_group 1;" ::: "memory")
#define CP_WAIT0()  asm volatile("cp.async.wait_group 0;" ::: "memory")

__device__ __forceinline__ uint32_t pack2bf(float x, float y) {
    __nv_bfloat162 t = __floats2bfloat162_rn(x, y);
    return *(uint32_t*)&t;
}
__device__ __forceinline__ float bf_res(float x) {       // x - bf16(x)
    return x - __bfloat162float(__float2bfloat16_rn(x));
}

// ---------------------------------------------------------------------------
// Kernel 0: fp32 -> bf16 hi/lo split converter (vectorized by 4)
// ---------------------------------------------------------------------------
__global__ void convert_kernel(const float* __restrict__ src,
                               __nv_bfloat16* __restrict__ hi,
                               __nv_bfloat16* __restrict__ lo, int n4)
{
    const int i = blockIdx.x * 256 + threadIdx.x;
    if (i >= n4) return;
    float4 v = ((const float4*)src)[i];
    uint32_t h0 = pack2bf(v.x, v.y), h1 = pack2bf(v.z, v.w);
    uint32_t l0 = pack2bf(bf_res(v.x), bf_res(v.y));
    uint32_t l1 = pack2bf(bf_res(v.z), bf_res(v.w));
    ((uint2*)hi)[i] = make_uint2(h0, h1);
    ((uint2*)lo)[i] = make_uint2(l0, l1);
}

// ===========================================================================
// GEMM v2 (HMMA bf16x3, cp.async): C tile 128x128 = A[M,K] x W[N,K]^T
// A,B given as bf16 hi/lo pairs. 256 thr / 8 warps (4Mx2N), KC=32,
// double-buffered cp.async, 80B smem rows. 2 CTAs/SM.
// ===========================================================================
#define KC 32
#define NKC (KDIM / KC)            // 64
#define ROWB 80
#define MAT 10240                  // 128*80
#define STG (4 * MAT)              // 40960
#define G_SMEM_BYTES (2 * STG)     // 81920

template <int MODE>
__global__ __launch_bounds__(256, 2)
void gemm_bf16_kernel(const __nv_bfloat16* __restrict__ Ah,
                      const __nv_bfloat16* __restrict__ Al,
                      const __nv_bfloat16* __restrict__ W0h,
                      const __nv_bfloat16* __restrict__ W0l,
                      const __nv_bfloat16* __restrict__ W1h,
                      const __nv_bfloat16* __restrict__ W1l,
                      const __nv_bfloat16* __restrict__ W2h,
                      const __nv_bfloat16* __restrict__ W2l,
                      float* __restrict__ yout)
{
    extern __shared__ char sm[];
    const uint32_t sb = smem_u32(sm);
    const int tid  = threadIdx.x;
    const int wid  = tid >> 5;
    const int lane = tid & 31;
    const int m0   = blockIdx.y * 128;
    const int n0   = blockIdx.x * 128;

    const __nv_bfloat16* Bh;
    const __nv_bfloat16* Bl;
    float* out;
    if (MODE == 0) {
        if (blockIdx.z == 0)      { Bh = W0h; Bl = W0l; out = g_q; }
        else if (blockIdx.z == 1) { Bh = W1h; Bl = W1l; out = g_k; }
        else                      { Bh = W2h; Bl = W2l; out = g_v; }
    } else {
        Bh = W0h; Bl = W0l; out = yout;
    }

    // cp.async task: row = tid>>1, half = tid&1 (16 bf16 = two 16B chunks)
    const int crow  = tid >> 1;
    const int chalf = tid & 1;
    const size_t aoff = (size_t)(m0 + crow) * KDIM + chalf * 16;
    const size_t boff = (size_t)(n0 + crow) * KDIM + chalf * 16;
    const uint32_t sto = (uint32_t)(crow * ROWB + chalf * 32);

    // issue one stage
    auto issue = [&](int kc, int buf) {
        const uint32_t st = sb + buf * STG + sto;
        const size_t ko = (size_t)kc * KC;
        CP16(st,                 Ah + aoff + ko);
        CP16(st + 16,            Ah + aoff + ko + 8);
        CP16(st + MAT,           Al + aoff + ko);
        CP16(st + MAT + 16,      Al + aoff + ko + 8);
        CP16(st + 2 * MAT,       Bh + boff + ko);
        CP16(st + 2 * MAT + 16,  Bh + boff + ko + 8);
        CP16(st + 3 * MAT,       Bl + boff + ko);
        CP16(st + 3 * MAT + 16,  Bl + boff + ko + 8);
        CP_COMMIT();
    };

    const int wm = wid & 3;
    const int wn = wid >> 2;
    const int r   = lane & 7;
    const int sel = lane >> 3;
    const uint32_t aBase = (uint32_t)((wm * 32 + r + (sel & 1) * 8) * ROWB +
                                      (sel >> 1) * 16);
    const uint32_t bBase = (uint32_t)((wn * 64 + r + (sel >> 1) * 8) * ROWB +
                                      (sel & 1) * 16);

    float acc[2][8][4];
#pragma unroll
    for (int i = 0; i < 2; i++)
#pragma unroll
        for (int j = 0; j < 8; j++)
#pragma unroll
            for (int t = 0; t < 4; t++) acc[i][j][t] = 0.f;

    issue(0, 0);
    for (int kc = 0; kc < NKC; ++kc) {
        const int cur = kc & 1;
        if (kc + 1 < NKC) { issue(kc + 1, cur ^ 1); CP_WAIT1(); }
        else              { CP_WAIT0(); }
        __syncthreads();

        const uint32_t stage = sb + cur * STG;
#pragma unroll
        for (int ks = 0; ks < 2; ++ks) {
            const uint32_t koff = ks * 32;
            uint32_t ah[2][4], al[2][4];
#pragma unroll
            for (int i = 0; i < 2; ++i) {
                const uint32_t aA = stage + aBase + i * (16 * ROWB) + koff;
                ldsm4(aA, ah[i]);
                ldsm4(aA + MAT, al[i]);
            }
#pragma unroll
            for (int j = 0; j < 4; ++j) {
                const uint32_t bA = stage + 2 * MAT + bBase + j * (16 * ROWB) + koff;
                uint32_t bh[4], bl[4];
                ldsm4(bA, bh);
                ldsm4(bA + MAT, bl);
#pragma unroll
                for (int i = 0; i < 2; ++i) {
#pragma unroll
                    for (int t = 0; t < 2; ++t) {
                        mma16816(acc[i][j * 2 + t], ah[i], bh[2 * t], bh[2 * t + 1]);
                        mma16816(acc[i][j * 2 + t], ah[i], bl[2 * t], bl[2 * t + 1]);
                        mma16816(acc[i][j * 2 + t], al[i], bh[2 * t], bh[2 * t + 1]);
                    }
                }
            }
        }
        __syncthreads();   // all reads done before next issue overwrites
    }

    // Epilogue (layout validated in R4)
#pragma unroll
    for (int i = 0; i < 2; ++i) {
        const int mrow = m0 + wm * 32 + i * 16 + (lane >> 2);
#pragma unroll
        for (int j = 0; j < 8; ++j) {
            const int ncol = n0 + wn * 64 + j * 8 + 2 * (lane & 3);
            float2 v01 = make_float2(acc[i][j][0], acc[i][j][1]);
            float2 v23 = make_float2(acc[i][j][2], acc[i][j][3]);
            if (MODE == 0) {
                const int b = mrow >> 11;
                const int t = mrow & 2047;
                const int h = ncol >> 7;
                const int d = ncol & 127;
                float* dst = &out[(((size_t)(b * NH + h)) * TSEQ + t) * HD + d];
                *(float2*)dst = v01;
                *(float2*)(dst + (size_t)8 * HD) = v23;
            } else {
                float* dst = &out[(size_t)mrow * DIM + ncol];
                *(float2*)dst = v01;
                *(float2*)(dst + (size_t)8 * DIM) = v23;
            }
        }
    }
}

// ---------------------------------------------------------------------------
// Kernel 2: RoPE + sqk*RESTORE (+ATTN_SCALE on q) and bf16 hi/lo conversion
// of q, k, v. One block per (b,h,t) row, 64 threads.
// ---------------------------------------------------------------------------
__global__ void rope_kernel(const float* __restrict__ sqk)
{
    const int row = blockIdx.x;
    const int j   = threadIdx.x;      // 0..63
    const int bh  = row >> 11;
    const int t   = row & 2047;
    const int h   = bh & (NH - 1);
    const size_t base = (size_t)row * HD;

    const double theta = exp(-(double)j * (9.210340371976184 / 64.0));
    const double ang   = (double)t * theta;
    double sd, cd;
    sincos(ang, &sd, &cd);
    const float c = (float)cd, s = (float)sd;

    const float s1 = sqk[h * HD + j]      * RESTORE_SCALE;
    const float s2 = sqk[h * HD + 64 + j] * RESTORE_SCALE;

    float qr = g_q[base + j], qi = g_q[base + 64 + j];
    float q1 = (qr * c - qi * s) * s1 * ATTN_SCALE;
    float q2 = (qr * s + qi * c) * s2 * ATTN_SCALE;
    g_qh[base + j]      = __float2bfloat16_rn(q1);
    g_ql[base + j]      = __float2bfloat16_rn(bf_res(q1));
    g_qh[base + 64 + j] = __float2bfloat16_rn(q2);
    g_ql[base + 64 + j] = __float2bfloat16_rn(bf_res(q2));

    float kr = g_k[base + j], ki = g_k[base + 64 + j];
    float k1 = (kr * c - ki * s) * s1;
    float k2 = (kr * s + ki * c) * s2;
    g_kh[base + j]      = __float2bfloat16_rn(k1);
    g_kl[base + j]      = __float2bfloat16_rn(bf_res(k1));
    g_kh[base + 64 + j] = __float2bfloat16_rn(k2);
    g_kl[base + 64 + j] = __float2bfloat16_rn(bf_res(k2));

    float v1 = g_v[base + j], v2 = g_v[base + 64 + j];
    g_vh[base + j]      = __float2bfloat16_rn(v1);
    g_vl[base + j]      = __float2bfloat16_rn(bf_res(v1));
    g_vh[base + 64 + j] = __float2bfloat16_rn(v2);
    g_vl[base + 64 + j] = __float2bfloat16_rn(bf_res(v2));
}

// ===========================================================================
// Kernel 3: causal flash attention on HMMA. BR=128, BC=64, 8 warps.
// Warp w owns q rows [16w,16w+16). QK^T: bf16x3 (hh+hl+lh).
// PV: PhVh + PhVl + PlVh with V b-frags via ldmatrix.x4.trans.
// Writes attention output as bf16 hi/lo (g_ah/g_al) for the out projection.
// ===========================================================================
#define FB_ROWB 272                      // 128 bf16 + 16B pad
#define F_QH 0
#define F_QL 34816                       // 128*272
#define F_KV 69632                       // stage base
#define F_KVSTG 69632                    // per stage: Kh,Kl,Vh,Vl @ 17408 each
#define F_SMEM_BYTES (F_KV + 2 * F_KVSTG)   // 208,896

__global__ __launch_bounds__(256, 1)
void flash_hmma_kernel()
{
    extern __shared__ char sm[];
    const uint32_t sb = smem_u32(sm);
    const int tid  = threadIdx.x;
    const int w    = tid >> 5;
    const int lane = tid & 31;
    // schedule longest CTAs (largest i0) first
    const int i0   = (int)(gridDim.x - 1 - blockIdx.x) * 128;
    const int bh   = blockIdx.y;
    const int b    = bh >> 4;
    const int h    = bh & 15;
    const size_t kvbase = (size_t)bh * TSEQ * HD;

    // ---- prologue: cp.async Q (hi+lo) and KV tile 0 ----
    {
        const size_t qgbase = kvbase + (size_t)i0 * HD;
#pragma unroll
        for (int it = 0; it < 16; ++it) {
            const int idx = (it & 7) * 256 + tid;     // 0..2047
            const int row = idx >> 4;
            const int ch  = idx & 15;
            const uint32_t dst = sb + ((it < 8) ? F_QH : F_QL) +
                                 row * FB_ROWB + ch * 16;
            const __nv_bfloat16* src = (it < 8) ? g_qh : g_ql;
            CP16(dst, src + qgbase + (size_t)row * HD + ch * 8);
        }
#pragma unroll
        for (int it = 0; it < 16; ++it) {
            const int mat = it >> 2;                  // 0:Kh 1:Kl 2:Vh 3:Vl
            const int idx = (it & 3) * 256 + tid;     // 0..1023
            const int row = idx >> 4;
            const int ch  = idx & 15;
            const uint32_t dst = sb + F_KV + mat * 17408 +
                                 row * FB_ROWB + ch * 16;
            const __nv_bfloat16* src = (mat == 0) ? g_kh : (mat == 1) ? g_kl
                                     : (mat == 2) ? g_vh : g_vl;
            CP16(dst, src + kvbase + (size_t)row * HD + ch * 8);
        }
        CP_COMMIT();
    }

    // ldmatrix lane bases
    const int r   = lane & 7;
    const int sel = lane >> 3;
    const uint32_t qBase = (uint32_t)((w * 16 + r + (sel & 1) * 8) * FB_ROWB +
                                      (sel >> 1) * 16);
    const uint32_t kBase = (uint32_t)((r + (sel >> 1) * 8) * FB_ROWB +
                                      (sel & 1) * 16);
    const uint32_t vBase = (uint32_t)(((sel & 1) * 8 + r) * FB_ROWB +
                                      (sel >> 1) * 16);

    float o[16][4];
#pragma unroll
    for (int i = 0; i < 16; i++)
#pragma unroll
        for (int t = 0; t < 4; t++) o[i][t] = 0.f;
    float m1 = -1e30f, m2 = -1e30f, l1 = 0.f, l2 = 0.f;
    const int grow1 = i0 + w * 16 + (lane >> 2);
    const int grow2 = grow1 + 8;

    const int ntiles = (i0 >> 6) + 2;
    for (int jt = 0; jt < ntiles; ++jt) {
        const int j0 = jt * 64;
        // prefetch next KV tile
        if (jt + 1 < ntiles) {
            const int nj0 = j0 + 64;
            const uint32_t stg = sb + F_KV + ((jt + 1) & 1) * F_KVSTG;
#pragma unroll
            for (int it = 0; it < 16; ++it) {
                const int mat = it >> 2;
                const int idx = (it & 3) * 256 + tid;
                const int row = idx >> 4;
                const int ch  = idx & 15;
                const uint32_t dst = stg + mat * 17408 + row * FB_ROWB + ch * 16;
                const __nv_bfloat16* src = (mat == 0) ? g_kh : (mat == 1) ? g_kl
                                         : (mat == 2) ? g_vh : g_vl;
                CP16(dst, src + kvbase + (size_t)(nj0 + row) * HD + ch * 8);
            }
            CP_COMMIT();
            CP_WAIT1();
        } else {
            CP_WAIT0();
        }
        __syncthreads();

        const uint32_t stg = sb + F_KV + (jt & 1) * F_KVSTG;
        const uint32_t KH = stg, KL = stg + 17408;
        const uint32_t VH = stg + 34816, VL = stg + 52224;

        // ---- S = Q K^T (bf16x3), per warp 16x64 ----
        float s[8][4];
#pragma unroll
        for (int i = 0; i < 8; i++)
#pragma unroll
            for (int t = 0; t < 4; t++) s[i][t] = 0.f;

#pragma unroll
        for (int kk = 0; kk < 8; ++kk) {
            uint32_t ah[4], al[4];
            ldsm4(sb + F_QH + qBase + kk * 32, ah);
            ldsm4(sb + F_QL + qBase + kk * 32, al);
#pragma unroll
            for (int j = 0; j < 4; ++j) {
                const uint32_t kA = kBase + j * (16 * FB_ROWB) + kk * 32;
                uint32_t bh[4], bl[4];
                ldsm4(KH + kA, bh);
                ldsm4(KL + kA, bl);
#pragma unroll
                for (int t = 0; t < 2; ++t) {
                    mma16816(s[j * 2 + t], ah, bh[2 * t], bh[2 * t + 1]);
                    mma16816(s[j * 2 + t], ah, bl[2 * t], bl[2 * t + 1]);
                    mma16816(s[j * 2 + t], al, bh[2 * t], bh[2 * t + 1]);
                }
            }
        }

        // ---- causal mask ----
        if (j0 + 63 > i0 + w * 16) {
#pragma unroll
            for (int t8 = 0; t8 < 8; ++t8) {
                const int gcol = j0 + t8 * 8 + 2 * (lane & 3);
                if (gcol > grow1)     s[t8][0] = -1e30f;
                if (gcol + 1 > grow1) s[t8][1] = -1e30f;
                if (gcol > grow2)     s[t8][2] = -1e30f;
                if (gcol + 1 > grow2) s[t8][3] = -1e30f;
            }
        }

        // ---- online softmax (rows owned within lane quads) ----
        float nm1 = m1, nm2 = m2;
#pragma unroll
        for (int t8 = 0; t8 < 8; ++t8) {
            nm1 = fmaxf(nm1, fmaxf(s[t8][0], s[t8][1]));
            nm2 = fmaxf(nm2, fmaxf(s[t8][2], s[t8][3]));
        }
        nm1 = fmaxf(nm1, __shfl_xor_sync(0xffffffffu, nm1, 1));
        nm1 = fmaxf(nm1, __shfl_xor_sync(0xffffffffu, nm1, 2));
        nm2 = fmaxf(nm2, __shfl_xor_sync(0xffffffffu, nm2, 1));
        nm2 = fmaxf(nm2, __shfl_xor_sync(0xffffffffu, nm2, 2));
        const float a1 = __expf(m1 - nm1);
        const float a2 = __expf(m2 - nm2);
        float r1 = 0.f, r2 = 0.f;
#pragma unroll
        for (int t8 = 0; t8 < 8; ++t8) {
            s[t8][0] = __expf(s[t8][0] - nm1);
            s[t8][1] = __expf(s[t8][1] - nm1);
            s[t8][2] = __expf(s[t8][2] - nm2);
            s[t8][3] = __expf(s[t8][3] - nm2);
            r1 += s[t8][0] + s[t8][1];
            r2 += s[t8][2] + s[t8][3];
        }
        r1 += __shfl_xor_sync(0xffffffffu, r1, 1);
        r1 += __shfl_xor_sync(0xffffffffu, r1, 2);
        r2 += __shfl_xor_sync(0xffffffffu, r2, 1);
        r2 += __shfl_xor_sync(0xffffffffu, r2, 2);
        l1 = l1 * a1 + r1;
        l2 = l2 * a2 + r2;
        m1 = nm1; m2 = nm2;
#pragma unroll
        for (int i = 0; i < 16; ++i) {
            o[i][0] *= a1; o[i][1] *= a1;
            o[i][2] *= a2; o[i][3] *= a2;
        }

        // ---- O += P V (PhVh + PlVh + PhVl) ----
#pragma unroll
        for (int kk = 0; kk < 4; ++kk) {
            uint32_t pah[4], pal[4];
            {
                const float* p0 = s[2 * kk];
                const float* p1 = s[2 * kk + 1];
                pah[0] = pack2bf(p0[0], p0[1]);
                pah[1] = pack2bf(p0[2], p0[3]);
                pah[2] = pack2bf(p1[0], p1[1]);
                pah[3] = pack2bf(p1[2], p1[3]);
                pal[0] = pack2bf(bf_res(p0[0]), bf_res(p0[1]));
                pal[1] = pack2bf(bf_res(p0[2]), bf_res(p0[3]));
                pal[2] = pack2bf(bf_res(p1[0]), bf_res(p1[1]));
                pal[3] = pack2bf(bf_res(p1[2]), bf_res(p1[3]));
            }
#pragma unroll
            for (int dt = 0; dt < 8; ++dt) {
                const uint32_t vA = vBase + kk * (16 * FB_ROWB) + dt * 32;
                uint32_t bh[4], bl[4];
                ldsm4t(VH + vA, bh);
                ldsm4t(VL + vA, bl);
#pragma unroll
                for (int t = 0; t < 2; ++t) {
                    mma16816(o[dt * 2 + t], pah, bh[2 * t], bh[2 * t + 1]);
                    mma16816(o[dt * 2 + t], pal, bh[2 * t], bh[2 * t + 1]);
                    mma16816(o[dt * 2 + t], pah, bl[2 * t], bl[2 * t + 1]);
                }
            }
        }
        __syncthreads();   // PV reads done before next prefetch overwrites
    }

    // ---- epilogue: divide by l, write bf16 hi/lo att ----
    const float inv1 = 1.0f / l1;
    const float inv2 = 1.0f / l2;
#pragma unroll
    for (int ot = 0; ot < 16; ++ot) {
        const int cold = ot * 8 + 2 * (lane & 3);
        const size_t i1 = ((size_t)(b * TSEQ + grow1)) * DIM + h * HD + cold;
        const size_t i2 = ((size_t)(b * TSEQ + grow2)) * DIM + h * HD + cold;
        const float v0 = o[ot][0] * inv1, v1 = o[ot][1] * inv1;
        const float v2 = o[ot][2] * inv2, v3 = o[ot][3] * inv2;
        *(uint32_t*)&g_ah[i1] = pack2bf(v0, v1);
        *(uint32_t*)&g_al[i1] = pack2bf(bf_res(v0), bf_res(v1));
        *(uint32_t*)&g_ah[i2] = pack2bf(v2, v3);
        *(uint32_t*)&g_al[i2] = pack2bf(bf_res(v2), bf_res(v3));
    }
}

// ---------------------------------------------------------------------------
// Kernel 5: per-row L2 normalization of y (in place on d_out)
// ---------------------------------------------------------------------------
__global__ void norm_kernel(float* __restrict__ y)
{
    const int row = blockIdx.x;
    float4* p = (float4*)(y + (size_t)row * DIM);
    float ss = 0.f;
#pragma unroll
    for (int i = threadIdx.x; i < DIM / 4; i += 256) {
        float4 v = p[i];
        ss += v.x * v.x + v.y * v.y + v.z * v.z + v.w * v.w;
    }
    ss += __shfl_xor_sync(0xffffffffu, ss, 16);
    ss += __shfl_xor_sync(0xffffffffu, ss, 8);
    ss += __shfl_xor_sync(0xffffffffu, ss, 4);
    ss += __shfl_xor_sync(0xffffffffu, ss, 2);
    ss += __shfl_xor_sync(0xffffffffu, ss, 1);
    __shared__ float red[8];
    if ((threadIdx.x & 31) == 0) red[threadIdx.x >> 5] = ss;
    __syncthreads();
    float tot = red[0] + red[1] + red[2] + red[3] +
                red[4] + red[5] + red[6] + red[7];
    const float inv = 1.0f / fmaxf(sqrtf(tot), 1e-12f);
#pragma unroll
    for (int i = threadIdx.x; i < DIM / 4; i += 256) {
        float4 v = p[i];
        v.x *= inv; v.y *= inv; v.z *= inv; v.w *= inv;
        p[i] = v;
    }
}

// ---------------------------------------------------------------------------
// Launch
// ---------------------------------------------------------------------------
extern "C" void kernel_launch(void* const* d_in, const int* in_sizes, int n_in,
                              void* d_out, int out_size)
{
    const float* x   = (const float*)d_in[0];
    const float* Wq  = (const float*)d_in[1];
    const float* Wk  = (const float*)d_in[2];
    const float* Wv  = (const float*)d_in[3];
    const float* Wo  = (const float*)d_in[4];
    const float* sqk = (const float*)d_in[5];
    float* y = (float*)d_out;

    __nv_bfloat16 *xh, *xl, *wqh, *wql, *wkh, *wkl, *wvh, *wvl, *woh, *wol;
    __nv_bfloat16 *ah, *al;
    cudaGetSymbolAddress((void**)&xh,  g_xh);
    cudaGetSymbolAddress((void**)&xl,  g_xl);
    cudaGetSymbolAddress((void**)&wqh, g_wqh);
    cudaGetSymbolAddress((void**)&wql, g_wql);
    cudaGetSymbolAddress((void**)&wkh, g_wkh);
    cudaGetSymbolAddress((void**)&wkl, g_wkl);
    cudaGetSymbolAddress((void**)&wvh, g_wvh);
    cudaGetSymbolAddress((void**)&wvl, g_wvl);
    cudaGetSymbolAddress((void**)&woh, g_woh);
    cudaGetSymbolAddress((void**)&wol, g_wol);
    cudaGetSymbolAddress((void**)&ah,  g_ah);
    cudaGetSymbolAddress((void**)&al,  g_al);

    cudaFuncSetAttribute(flash_hmma_kernel,
                         cudaFuncAttributeMaxDynamicSharedMemorySize,
                         F_SMEM_BYTES);
    cudaFuncSetAttribute(gemm_bf16_kernel<0>,
                         cudaFuncAttributeMaxDynamicSharedMemorySize,
                         G_SMEM_BYTES);
    cudaFuncSetAttribute(gemm_bf16_kernel<1>,
                         cudaFuncAttributeMaxDynamicSharedMemorySize,
                         G_SMEM_BYTES);

    const int NX = MROWS * DIM / 4;    // 2.1M float4
    const int NW = DIM * DIM / 4;
    convert_kernel<<<(NX + 255) / 256, 256>>>(x,  xh,  xl,  NX);
    convert_kernel<<<(NW + 255) / 256, 256>>>(Wq, wqh, wql, NW);
    convert_kernel<<<(NW + 255) / 256, 256>>>(Wk, wkh, wkl, NW);
    convert_kernel<<<(NW + 255) / 256, 256>>>(Wv, wvh, wvl, NW);
    convert_kernel<<<(NW + 255) / 256, 256>>>(Wo, woh, wol, NW);

    gemm_bf16_kernel<0><<<dim3(DIM / 128, MROWS / 128, 3), 256, G_SMEM_BYTES>>>(
        xh, xl, wqh, wql, wkh, wkl, wvh, wvl, nullptr);
    rope_kernel<<<BATCH * NH * TSEQ, 64>>>(sqk);
    flash_hmma_kernel<<<dim3(TSEQ / 128, BATCH * NH), 256, F_SMEM_BYTES>>>();
    gemm_bf16_kernel<1><<<dim3(DIM / 128, MROWS / 128, 1), 256, G_SMEM_BYTES>>>(
        ah, al, woh, wol, nullptr, nullptr, nullptr, nullptr, y);
    norm_kernel<<<MROWS, 256>>>(y);
}